// round 3
// baseline (speedup 1.0000x reference)
#include <cuda_runtime.h>
#include <cstdint>

#define BB 128
#define NN 1000
#define DD 196
#define KK 48
#define NWARPS 32
#define THREADS (NWARPS * 32)

__global__ __launch_bounds__(THREADS, 1)
void ptk_kernel(const float* __restrict__ x,
                const float* __restrict__ noise,
                const float* __restrict__ sigma_p,
                float* __restrict__ out)
{
    __shared__ int acc[KK * DD];   // 48*196*4 = 37632 B

    const int b    = blockIdx.x;
    const int tid  = threadIdx.x;
    const int lane = tid & 31;
    const int warp = tid >> 5;

    for (int i = tid; i < KK * DD; i += THREADS) acc[i] = 0;
    __syncthreads();

    const float sigma = sigma_p ? *sigma_p : 0.05f;

    // Preload this lane's x columns: d = 32*j + lane
    float xv[7];
#pragma unroll
    for (int j = 0; j < 7; ++j) {
        int d = j * 32 + lane;
        xv[j] = (d < DD) ? x[b * DD + d] : 0.0f;
    }

    const float* nbase = noise + (size_t)b * NN * DD;
    const unsigned lt = (1u << lane) - 1u;

    for (int n = warp; n < NN; n += NWARPS) {
        const float* row = nbase + (size_t)n * DD;

        // Load + build sortable keys (index tie-break handled at threshold).
        unsigned key[7];
#pragma unroll
        for (int j = 0; j < 7; ++j) {
            int d = j * 32 + lane;
            if (d < DD) {
                float v = fmaf(sigma, row[d], xv[j]);
                unsigned u = __float_as_uint(v);
                key[j] = u ^ ((unsigned)((int)u >> 31) | 0x80000000u);
            } else {
                key[j] = 0u;   // strictly below any finite-value key
            }
        }

        // Warp radix-select: exact 48th-largest key.
        unsigned prefix = 0;
        int rem = KK;
#pragma unroll
        for (int bit = 31; bit >= 0; --bit) {
            unsigned want = (prefix >> bit) | 1u;
            int c = 0;
#pragma unroll
            for (int j = 0; j < 7; ++j) c += ((key[j] >> bit) == want);
            c = __reduce_add_sync(0xffffffffu, c);
            if (c >= rem) prefix |= (1u << bit);
            else          rem -= c;
        }
        // prefix = threshold key T; rem = # of ==T elements to take (lowest index first)

        // Selection + rank-by-index + scatter.
        int sel_before = 0, eq_before = 0;
#pragma unroll
        for (int j = 0; j < 7; ++j) {
            bool gt = key[j] > prefix;
            bool eq = key[j] == prefix;
            unsigned be = __ballot_sync(0xffffffffu, eq);
            int eq_rank = eq_before + __popc(be & lt);
            bool sel = gt || (eq && (eq_rank < rem));
            unsigned bs = __ballot_sync(0xffffffffu, sel);
            if (sel) {
                int rank = sel_before + __popc(bs & lt);
                int d = j * 32 + lane;
                atomicAdd(&acc[rank * DD + d], 1);
            }
            eq_before  += __popc(be);
            sel_before += __popc(bs);
        }
    }

    __syncthreads();

    const float inv = 1.0f / (float)NN;
    float* ob = out + (size_t)b * KK * DD;
    for (int i = tid; i < KK * DD; i += THREADS)
        ob[i] = (float)acc[i] * inv;
}

extern "C" void kernel_launch(void* const* d_in, const int* in_sizes, int n_in,
                              void* d_out, int out_size)
{
    const float* x     = nullptr;
    const float* noise = nullptr;
    const float* sigma = nullptr;
    for (int i = 0; i < n_in; ++i) {
        if      (in_sizes[i] == BB * DD)       x     = (const float*)d_in[i];
        else if (in_sizes[i] == BB * NN * DD)  noise = (const float*)d_in[i];
        else if (in_sizes[i] == 1)             sigma = (const float*)d_in[i];
    }
    ptk_kernel<<<BB, THREADS>>>(x, noise, sigma, (float*)d_out);
}

// round 4
// speedup vs baseline: 2.6717x; 2.6717x over previous
#include <cuda_runtime.h>
#include <cstdint>
#include <math.h>

#define BB 128
#define NN 1000
#define DD 196
#define KK 48
#define NC 64            // candidate columns (top-NC of x per batch row)
#define NO (DD - NC)     // 132 other columns
#define NWARPS 32
#define THREADS (NWARPS * 32)

__device__ __forceinline__ unsigned f2key(float v) {
    unsigned u = __float_as_uint(v);
    return u ^ ((unsigned)((int)u >> 31) | 0x80000000u);
}

// Exact full-width fallback: top-KK of all 196 perturbed values, d-ascending ranks.
__device__ __noinline__ void fallback_select(const float* __restrict__ row,
                                             const float* __restrict__ xb,
                                             float sigma, int* acc,
                                             int lane, unsigned lt)
{
    const unsigned FULL = 0xffffffffu;
    unsigned key[7];
#pragma unroll
    for (int j = 0; j < 7; ++j) {
        int d = j * 32 + lane;
        key[j] = (d < DD) ? f2key(fmaf(sigma, row[d], xb[d])) : 0u;
    }
    unsigned prefix = 0;
    for (int bit = 31; bit >= 0; --bit) {
        unsigned t = prefix | (1u << bit);
        int c = 0;
#pragma unroll
        for (int j = 0; j < 7; ++j) c += (key[j] >= t);
        c = __reduce_add_sync(FULL, c);
        if (c >= KK) { prefix = t; if (c == KK) break; }
    }
    int cgt = 0;
#pragma unroll
    for (int j = 0; j < 7; ++j) cgt += (key[j] > prefix);
    cgt = __reduce_add_sync(FULL, cgt);
    int rem = KK - cgt;
    int selb = 0, eqb = 0;
#pragma unroll
    for (int j = 0; j < 7; ++j) {
        bool gt = key[j] > prefix;
        bool eq = (key[j] == prefix);
        unsigned be = __ballot_sync(FULL, eq);
        bool sel = gt || (eq && (eqb + __popc(be & lt)) < rem);
        unsigned bs = __ballot_sync(FULL, sel);
        if (sel) atomicAdd(&acc[(selb + __popc(bs & lt)) * DD + (j * 32 + lane)], 1);
        eqb += __popc(be);
        selb += __popc(bs);
    }
}

__global__ __launch_bounds__(THREADS, 1)
void ptk_kernel(const float* __restrict__ x,
                const float* __restrict__ noise,
                const float* __restrict__ sigma_p,
                float* __restrict__ out)
{
    __shared__ int acc[KK * DD];   // 37632 B
    __shared__ short cidx[NC];     // candidate column ids, ascending d
    __shared__ short oidx[NO];     // other column ids, ascending d

    const int b = blockIdx.x, tid = threadIdx.x, lane = tid & 31, warp = tid >> 5;
    const unsigned lt = (1u << lane) - 1u;
    const unsigned FULL = 0xffffffffu;

    for (int i = tid; i < KK * DD; i += THREADS) acc[i] = 0;

    // ---- per-b precompute (warp 0): exact top-NC columns of x ----
    if (warp == 0) {
        unsigned key[7];
#pragma unroll
        for (int j = 0; j < 7; ++j) {
            int d = j * 32 + lane;
            key[j] = (d < DD) ? f2key(x[b * DD + d]) : 0u;
        }
        unsigned prefix = 0;
        for (int bit = 31; bit >= 0; --bit) {
            unsigned t = prefix | (1u << bit);
            int c = 0;
#pragma unroll
            for (int j = 0; j < 7; ++j) c += (key[j] >= t);
            c = __reduce_add_sync(FULL, c);
            if (c >= NC) { prefix = t; if (c == NC) break; }
        }
        int cgt = 0;
#pragma unroll
        for (int j = 0; j < 7; ++j) cgt += (key[j] > prefix);
        cgt = __reduce_add_sync(FULL, cgt);
        int rem = NC - cgt;
        int cb = 0, ob = 0, eqb = 0;
#pragma unroll
        for (int j = 0; j < 7; ++j) {
            int d = j * 32 + lane;
            bool valid = d < DD;
            bool gt = key[j] > prefix;
            bool eq = valid && (key[j] == prefix);
            unsigned be = __ballot_sync(FULL, eq);
            bool sel = gt || (eq && (eqb + __popc(be & lt)) < rem);
            unsigned bs = __ballot_sync(FULL, sel);
            unsigned bo = __ballot_sync(FULL, valid && !sel);
            if (sel)        cidx[cb + __popc(bs & lt)] = (short)d;
            else if (valid) oidx[ob + __popc(bo & lt)] = (short)d;
            eqb += __popc(be); cb += __popc(bs); ob += __popc(bo);
        }
    }
    __syncthreads();

    const float sigma = sigma_p ? *sigma_p : 0.05f;
    const float* xb = x + b * DD;

    // per-lane static gather indices + x values
    const int dC0 = cidx[lane];
    const int dC1 = cidx[32 + lane];
    const float xC0 = xb[dC0];
    const float xC1 = xb[dC1];
    int dO[5]; float xO[5];
#pragma unroll
    for (int j = 0; j < 5; ++j) {
        int p = j * 32 + lane;
        if (p < NO) { dO[j] = oidx[p]; xO[j] = xb[dO[j]]; }
        else        { dO[j] = 0;       xO[j] = -INFINITY; }
    }

    const float* nbase = noise + (size_t)b * NN * DD;

    for (int n = warp; n < NN; n += NWARPS) {
        const float* row = nbase + (size_t)n * DD;

        // candidate keys
        unsigned k0 = f2key(fmaf(sigma, row[dC0], xC0));
        unsigned k1 = f2key(fmaf(sigma, row[dC1], xC1));

        // max over non-candidates
        float mo = -INFINITY;
#pragma unroll
        for (int j = 0; j < 5; ++j) mo = fmaxf(mo, fmaf(sigma, row[dO[j]], xO[j]));
        unsigned moK = __reduce_max_sync(FULL, f2key(mo));

        // common-prefix skip
        unsigned A = __reduce_and_sync(FULL, k0 & k1);
        unsigned O = __reduce_or_sync(FULL, k0 | k1);
        unsigned xr = A ^ O;
        unsigned vT;
        if (xr == 0u) {
            vT = A;
        } else {
            int hb = 31 - __clz(xr);
            unsigned prefix = (hb < 31) ? ((A >> (hb + 1)) << (hb + 1)) : 0u;
            for (int bit = hb; bit >= 0; --bit) {
                unsigned t = prefix | (1u << bit);
                int c = (int)(k0 >= t) + (int)(k1 >= t);
                c = __reduce_add_sync(FULL, c);
                if (c >= KK) { prefix = t; if (c == KK) break; }
            }
            vT = prefix;
        }

        if (moK >= vT) {
            // some non-candidate might enter top-48 (or tie): exact full path
            fallback_select(row, xb, sigma, acc, lane, lt);
            continue;
        }

        int cgt = __reduce_add_sync(FULL, (int)(k0 > vT) + (int)(k1 > vT));
        int rem = KK - cgt;

        // scatter (list is ascending-d, slot0 then slot1 = ascending rank order)
        int selb, eqb;
        {
            bool gt = k0 > vT, eq = (k0 == vT);
            unsigned be = __ballot_sync(FULL, eq);
            bool sel = gt || (eq && (__popc(be & lt)) < rem);
            unsigned bs = __ballot_sync(FULL, sel);
            if (sel) atomicAdd(&acc[(__popc(bs & lt)) * DD + dC0], 1);
            eqb = __popc(be); selb = __popc(bs);
        }
        {
            bool gt = k1 > vT, eq = (k1 == vT);
            unsigned be = __ballot_sync(FULL, eq);
            bool sel = gt || (eq && (eqb + __popc(be & lt)) < rem);
            unsigned bs = __ballot_sync(FULL, sel);
            if (sel) atomicAdd(&acc[(selb + __popc(bs & lt)) * DD + dC1], 1);
        }
    }

    __syncthreads();

    const float inv = 1.0f / (float)NN;
    float* ob = out + (size_t)b * KK * DD;
    for (int i = tid; i < KK * DD; i += THREADS)
        ob[i] = (float)acc[i] * inv;
}

extern "C" void kernel_launch(void* const* d_in, const int* in_sizes, int n_in,
                              void* d_out, int out_size)
{
    const float* x     = nullptr;
    const float* noise = nullptr;
    const float* sigma = nullptr;
    for (int i = 0; i < n_in; ++i) {
        if      (in_sizes[i] == BB * DD)      x     = (const float*)d_in[i];
        else if (in_sizes[i] == BB * NN * DD) noise = (const float*)d_in[i];
        else if (in_sizes[i] == 1)            sigma = (const float*)d_in[i];
    }
    ptk_kernel<<<BB, THREADS>>>(x, noise, sigma, (float*)d_out);
}